// round 10
// baseline (speedup 1.0000x reference)
#include <cuda_runtime.h>
#include <cstdint>
#include <cstddef>

// FlowNetC correlation: out[b, dy*9+dx, y, x] = (1/C) * sum_c in1[b,c,y,x] * in2[b,c,y+dy-4,x+dx-4]
// (zero outside bounds). Shapes fixed: C=256, H=96, W=128, 81 displacement channels.

#define C_CH 256
#define H_IN 96
#define W_IN 128
#define ND   9          // displacements per axis
#define MD   4          // max displacement
#define TY   8          // tile rows per CTA
#define TX   32         // tile cols per CTA
#define CK   8          // channels per SMEM stage
#define SY   (TY + 2*MD)   // 16 haloed rows of in2
#define SX   (TX + 2*MD)   // 40 haloed cols of in2
#define NTHREADS 576       // (TX/4)*TY quads * ND dy-groups = 64*9
#define S1_FLOATS (CK*TY*TX)    // 2048
#define S2_FLOATS (CK*SY*SX)    // 5120
#define BUF_FLOATS (S1_FLOATS + S2_FLOATS)  // 7168
#define SMEM_BYTES (2*BUF_FLOATS*4)         // 57344 (double buffered)

__device__ __forceinline__ void cp_async16(uint32_t saddr, const float* gsrc, int src_bytes) {
    asm volatile("cp.async.cg.shared.global [%0], [%1], 16, %2;\n"
                 :: "r"(saddr), "l"(gsrc), "r"(src_bytes));
}
__device__ __forceinline__ void cp_commit() {
    asm volatile("cp.async.commit_group;\n" ::: "memory");
}
__device__ __forceinline__ void cp_wait1() {
    asm volatile("cp.async.wait_group 1;\n" ::: "memory");
}

__device__ __forceinline__ void issue_stage(uint32_t smem_base, int buf, int c0,
                                            const float* __restrict__ in1b,
                                            const float* __restrict__ in2b,
                                            int ty0, int tx0, int tid) {
    uint32_t s1a = smem_base + (uint32_t)buf * (BUF_FLOATS * 4);
    uint32_t s2a = s1a + S1_FLOATS * 4;

    // in1 tile: CK x TY x TX, always fully in bounds, 16B-aligned float4 copies.
    #pragma unroll 1
    for (int i = tid; i < S1_FLOATS / 4; i += NTHREADS) {
        int col4 = i & 7;           // 8 float4 per 32-wide row
        int row  = (i >> 3) & 7;    // TY
        int cc   = i >> 6;          // CK
        const float* src = in1b + ((size_t)(c0 + cc) * H_IN + (ty0 + row)) * W_IN
                                + tx0 + col4 * 4;
        cp_async16(s1a + (uint32_t)i * 16, src, 16);
    }
    // in2 haloed tile: CK x SY x SX. OOB float4s are exactly aligned to the
    // 4-wide halo (W%4==0, MD==4), so each float4 is fully in or fully out:
    // out-of-bounds copies use src-size 0 => hardware zero-fill.
    #pragma unroll 1
    for (int i = tid; i < S2_FLOATS / 4; i += NTHREADS) {
        int col4 = i % (SX / 4);            // 10 float4 per row
        int row  = (i / (SX / 4)) % SY;     // 16 rows
        int cc   = i / ((SX / 4) * SY);     // CK
        int gx = tx0 + col4 * 4 - MD;
        int gy = ty0 + row - MD;
        bool ok = (gy >= 0) & (gy < H_IN) & (gx >= 0) & (gx <= W_IN - 4);
        const float* src = in2b + ((size_t)(c0 + cc) * H_IN + (ok ? gy : 0)) * W_IN
                                + (ok ? gx : 0);
        cp_async16(s2a + (uint32_t)i * 16, src, ok ? 16 : 0);
    }
}

__global__ void __launch_bounds__(NTHREADS, 1)
Correlation_72164040507827_kernel(const float* __restrict__ in1,
                                  const float* __restrict__ in2,
                                  float* __restrict__ out) {
    extern __shared__ float smem[];
    const int tid = threadIdx.x;
    const int b   = blockIdx.z;
    const int ty0 = blockIdx.y * TY;
    const int tx0 = blockIdx.x * TX;

    // thread = (x-quad within tile, dy index)
    const int dyi = tid / 64;    // 0..8
    const int q   = tid % 64;
    const int qy  = q >> 3;      // 0..7
    const int qx  = q & 7;       // 0..7 (x-quad)

    float acc[ND][4];
    #pragma unroll
    for (int d = 0; d < ND; ++d)
        #pragma unroll
        for (int j = 0; j < 4; ++j) acc[d][j] = 0.0f;

    const float* in1b = in1 + (size_t)b * C_CH * (H_IN * W_IN);
    const float* in2b = in2 + (size_t)b * C_CH * (H_IN * W_IN);

    uint32_t smem_base = (uint32_t)__cvta_generic_to_shared(smem);

    issue_stage(smem_base, 0, 0, in1b, in2b, ty0, tx0, tid);
    cp_commit();

    const int nChunks = C_CH / CK;  // 32
    #pragma unroll 1
    for (int k = 0; k < nChunks; ++k) {
        if (k + 1 < nChunks)
            issue_stage(smem_base, (k + 1) & 1, (k + 1) * CK, in1b, in2b, ty0, tx0, tid);
        cp_commit();            // (possibly empty) group keeps wait_group accounting uniform
        cp_wait1();             // stage k resident
        __syncthreads();

        const float* s1 = smem + (size_t)(k & 1) * BUF_FLOATS;
        const float* s2 = s1 + S1_FLOATS;
        const float* s1p = s1 + qy * TX + qx * 4;
        const float* s2p = s2 + (qy + dyi) * SX + qx * 4;

        #pragma unroll
        for (int cc = 0; cc < CK; ++cc) {
            float4 a  = *(const float4*)(s1p + cc * (TY * TX));
            float4 r0 = *(const float4*)(s2p + cc * (SY * SX));
            float4 r1 = *(const float4*)(s2p + cc * (SY * SX) + 4);
            float4 r2 = *(const float4*)(s2p + cc * (SY * SX) + 8);
            float r[12] = {r0.x, r0.y, r0.z, r0.w,
                           r1.x, r1.y, r1.z, r1.w,
                           r2.x, r2.y, r2.z, r2.w};
            #pragma unroll
            for (int dx = 0; dx < ND; ++dx) {
                acc[dx][0] += a.x * r[dx + 0];
                acc[dx][1] += a.y * r[dx + 1];
                acc[dx][2] += a.z * r[dx + 2];
                acc[dx][3] += a.w * r[dx + 3];
            }
        }
        __syncthreads();  // all reads of buffer (k&1) done before it is refilled at k+1
    }

    // Epilogue: normalize and store. out[b][dyi*9+dx][y][x..x+3], float4, coalesced.
    const float scale = 1.0f / (float)C_CH;
    const int y = ty0 + qy;
    const int x = tx0 + qx * 4;
    #pragma unroll
    for (int dx = 0; dx < ND; ++dx) {
        float4 v;
        v.x = acc[dx][0] * scale;
        v.y = acc[dx][1] * scale;
        v.z = acc[dx][2] * scale;
        v.w = acc[dx][3] * scale;
        size_t o = (((size_t)b * (ND * ND) + dyi * ND + dx) * H_IN + y) * W_IN + x;
        *(float4*)(out + o) = v;
    }
}

extern "C" void kernel_launch(void* const* d_in, const int* in_sizes, int n_in,
                              void* d_out, int out_size) {
    const float* in1 = (const float*)d_in[0];
    const float* in2 = (const float*)d_in[1];
    float* out = (float*)d_out;

    int B = in_sizes[0] / (C_CH * H_IN * W_IN);

    static bool attr_set = false;
    if (!attr_set) {
        cudaFuncSetAttribute(Correlation_72164040507827_kernel,
                             cudaFuncAttributeMaxDynamicSharedMemorySize, SMEM_BYTES);
        attr_set = true;
    }

    dim3 grid(W_IN / TX, H_IN / TY, B);  // 4 x 12 x B
    Correlation_72164040507827_kernel<<<grid, NTHREADS, SMEM_BYTES>>>(in1, in2, out);
}